// round 7
// baseline (speedup 1.0000x reference)
#include <cuda_runtime.h>

// Problem constants (fixed by reference)
#define BB      4
#define HW      400
#define OUTD    100
#define STRIDEV 4
#define NPTS    10000          // OUTD*OUTD
#define NSPLIT  4              // source-dimension split for load balance
#define MSLICE  (NPTS/NSPLIT)  // 2500 sources per split
#define SRC_TILE 500           // smem tile (float4) -> 8 KB
#define TCHUNK  128            // threads per block == targets per block

// Scratch (device globals; no allocation allowed)
__device__ float4 g_t4[BB * NPTS];           // (-2x,-2y,-2z, |t|^2)
__device__ float4 g_s4[BB * NPTS];           // ( x,  y,  z, |s|^2)
__device__ float  g_part[BB * NSPLIT * NPTS];
__device__ float  g_bsum[BB];

// ---------------------------------------------------------------------------
// Phase 0: downsample + pack. idx < BB*NPTS -> target, else source.
// ---------------------------------------------------------------------------
__global__ void pack_kernel(const float* __restrict__ tp,
                            const float* __restrict__ sp) {
    int idx = blockIdx.x * blockDim.x + threadIdx.x;
    if (idx >= 2 * BB * NPTS) return;
    bool is_src = idx >= BB * NPTS;
    int lid = is_src ? idx - BB * NPTS : idx;
    int b = lid / NPTS;
    int n = lid - b * NPTS;
    int oh = n / OUTD;
    int ow = n - oh * OUTD;
    const float* p = is_src ? sp : tp;
    long base = (long)b * 3 * HW * HW + (long)(oh * STRIDEV) * HW + (ow * STRIDEV);
    float x = p[base];
    float y = p[base + HW * HW];
    float z = p[base + 2 * HW * HW];
    float sq = x * x + y * y + z * z;
    if (is_src) {
        g_s4[lid] = make_float4(x, y, z, sq);
    } else {
        g_t4[lid] = make_float4(-2.0f * x, -2.0f * y, -2.0f * z, sq);
    }
}

// ---------------------------------------------------------------------------
// Phase 1: brute-force partial min over a source slice.
// grid = (ceil(NPTS/TCHUNK), NSPLIT, BB), block = TCHUNK
// per pair: v = s.w + t'.x*s.x + t'.y*s.y + t'.z*s.z   (3 FFMA) ; fminf (1 FMNMX)
// ---------------------------------------------------------------------------
__global__ void __launch_bounds__(TCHUNK)
dist_kernel() {
    __shared__ float4 tile[SRC_TILE];

    int n     = blockIdx.x * TCHUNK + threadIdx.x;
    int split = blockIdx.y;
    int b     = blockIdx.z;

    float4 t = g_t4[b * NPTS + (n < NPTS ? n : 0)];

    float best0 = 3.4e38f, best1 = 3.4e38f;

    const float4* __restrict__ src = g_s4 + b * NPTS + split * MSLICE;

    for (int tb = 0; tb < MSLICE / SRC_TILE; ++tb) {
        __syncthreads();
        #pragma unroll
        for (int j = threadIdx.x; j < SRC_TILE; j += TCHUNK)
            tile[j] = src[tb * SRC_TILE + j];
        __syncthreads();

        #pragma unroll 5
        for (int j = 0; j < SRC_TILE; j += 2) {
            float4 s0 = tile[j];
            float4 s1 = tile[j + 1];
            float v0 = fmaf(t.x, s0.x, fmaf(t.y, s0.y, fmaf(t.z, s0.z, s0.w)));
            float v1 = fmaf(t.x, s1.x, fmaf(t.y, s1.y, fmaf(t.z, s1.z, s1.w)));
            best0 = fminf(best0, v0);
            best1 = fminf(best1, v1);
        }
    }

    if (n < NPTS)
        g_part[(b * NSPLIT + split) * NPTS + n] = fminf(best0, best1);
}

// ---------------------------------------------------------------------------
// Phase 2: per-batch combine splits, add |t|^2, deterministic block reduce.
// grid = BB, block = 256
// ---------------------------------------------------------------------------
__global__ void reduce_kernel() {
    __shared__ float ssum[256];
    int b = blockIdx.x;
    float acc = 0.0f;
    for (int n = threadIdx.x; n < NPTS; n += 256) {
        float m = g_part[(b * NSPLIT + 0) * NPTS + n];
        #pragma unroll
        for (int s = 1; s < NSPLIT; ++s)
            m = fminf(m, g_part[(b * NSPLIT + s) * NPTS + n]);
        acc += m + g_t4[b * NPTS + n].w;
    }
    ssum[threadIdx.x] = acc;
    __syncthreads();
    for (int ofs = 128; ofs > 0; ofs >>= 1) {
        if (threadIdx.x < ofs) ssum[threadIdx.x] += ssum[threadIdx.x + ofs];
        __syncthreads();
    }
    if (threadIdx.x == 0) g_bsum[b] = ssum[0];
}

// ---------------------------------------------------------------------------
// Phase 3: final scalar = sum / (B * N * 3)
// ---------------------------------------------------------------------------
__global__ void final_kernel(float* __restrict__ out) {
    float s = 0.0f;
    #pragma unroll
    for (int b = 0; b < BB; ++b) s += g_bsum[b];
    out[0] = s * (1.0f / (float)(BB * NPTS * 3));
}

extern "C" void kernel_launch(void* const* d_in, const int* in_sizes, int n_in,
                              void* d_out, int out_size) {
    const float* tp = (const float*)d_in[0];
    const float* sp = (const float*)d_in[1];
    float* out = (float*)d_out;

    int pack_threads = 2 * BB * NPTS;
    pack_kernel<<<(pack_threads + 255) / 256, 256>>>(tp, sp);

    dim3 grid((NPTS + TCHUNK - 1) / TCHUNK, NSPLIT, BB);
    dist_kernel<<<grid, TCHUNK>>>();

    reduce_kernel<<<BB, 256>>>();
    final_kernel<<<1, 1>>>(out);
}